// round 3
// baseline (speedup 1.0000x reference)
#include <cuda_runtime.h>
#include <cstdint>

// Problem constants
#define KH 16
#define KW 16
#define Bn 64
#define Hn 1024
#define Wn 1024
#define OH 1009
#define OW 1009

// Tiling
#define TILE_Y 64                 // output rows per block
#define TILE_X 96                 // output cols per block
#define CPT    12                 // cols per thread
#define TROWS  (TILE_Y + KH - 1)  // 79 input rows
#define TPITCH (TILE_X + KW - 1)  // 111 input cols (also smem pitch; conflict-free)
#define NTHREADS 256

typedef unsigned long long ull;

// Packed dual-FMA: d.lo = a.lo*b.lo + c.lo ; d.hi = a.hi*b.hi + c.hi
// This is the ONLY way to reach the 2x fp32 rate on sm_103a (FFMA2).
__device__ __forceinline__ ull fma2(ull a, ull b, ull c) {
    ull d;
    asm("fma.rn.f32x2 %0, %1, %2, %3;" : "=l"(d) : "l"(a), "l"(b), "l"(c));
    return d;
}

__device__ __forceinline__ ull pack2(unsigned lo, unsigned hi) {
    ull d;
    asm("mov.b64 %0, {%1, %2};" : "=l"(d) : "r"(lo), "r"(hi));
    return d;
}

__global__ __launch_bounds__(NTHREADS, 2)
void conv2d_f32x2_kernel(const float* __restrict__ x,
                         const float* __restrict__ kern,
                         float* __restrict__ out)
{
    __shared__ float  T[TROWS * TPITCH];   // input tile (plain, 35KB)
    __shared__ float2 wdup[KH * KW];       // duplicated (w,w) weight pairs

    const int tid = threadIdx.x;
    const int b   = blockIdx.z;
    const int gy0 = blockIdx.y * TILE_Y;
    const int gx0 = blockIdx.x * TILE_X;

    const float* __restrict__ xb = x + (size_t)b * (Hn * (size_t)Wn);

    // ---- fill weight pairs (broadcastable via LDS.64) ----
    if (tid < KH * KW) {
        float w = kern[tid];
        wdup[tid] = make_float2(w, w);
    }

    // ---- fill input tile (clamped reads; clamped values only feed discarded outputs) ----
    for (int idx = tid; idx < TROWS * TPITCH; idx += NTHREADS) {
        int r = idx / TPITCH;
        int c = idx - r * TPITCH;
        int gy = gy0 + r; if (gy > Hn - 1) gy = Hn - 1;
        int gx = gx0 + c; if (gx > Wn - 1) gx = Wn - 1;
        T[idx] = xb[(size_t)gy * Wn + gx];
    }
    __syncthreads();

    // Thread mapping: 8 col-groups x 32 row-slots.
    // Row slot -> output row PAIR (16g+u, 16g+u+8): both f32x2 lanes share the
    // same weight for every tap, so the broadcast (w,w) operand is exact.
    const int tx   = tid & 7;
    const int tyi  = tid >> 3;
    const int g    = tyi >> 3;      // 0..3
    const int u    = tyi & 7;       // 0..7
    const int arow = 16 * g + u;    // lo output row within tile (0..55)
    const int c0   = tx * CPT;      // 0..84

    ull acc[CPT];
    #pragma unroll
    for (int j = 0; j < CPT; j++) acc[j] = 0ull;

    const ull* __restrict__ wp64 = reinterpret_cast<const ull*>(wdup);

    #pragma unroll 1   // keep body ~4.6KB -> I-cache resident
    for (int ky = 0; ky < KH; ky++) {
        const float* rowLo = &T[(arow + ky) * TPITCH + c0];
        const float* rowHi = rowLo + 8 * TPITCH;

        // Sliding window of packed (rowLo, rowHi) pairs, reused across all 16 kx.
        ull win[CPT + KW - 1];
        #pragma unroll
        for (int j = 0; j < CPT + KW - 1; j++)
            win[j] = pack2(__float_as_uint(rowLo[j]), __float_as_uint(rowHi[j]));

        #pragma unroll
        for (int kx = 0; kx < KW; kx++) {
            ull w2 = wp64[ky * KW + kx];   // uniform -> broadcast LDS.64
            #pragma unroll
            for (int j = 0; j < CPT; j++)
                acc[j] = fma2(win[j + kx], w2, acc[j]);
        }
    }

    // ---- epilogue: unpack pairs, guarded stores ----
    const int oyLo = gy0 + arow;
    const int oyHi = oyLo + 8;
    float* __restrict__ outb = out + (size_t)b * (OH * (size_t)OW);

    #pragma unroll
    for (int j = 0; j < CPT; j++) {
        int ox = gx0 + c0 + j;
        if (ox < OW) {
            float lo = __uint_as_float((unsigned)(acc[j] & 0xFFFFFFFFull));
            float hi = __uint_as_float((unsigned)(acc[j] >> 32));
            if (oyLo < OH) outb[(size_t)oyLo * OW + ox] = lo;
            if (oyHi < OH) outb[(size_t)oyHi * OW + ox] = hi;
        }
    }
}

extern "C" void kernel_launch(void* const* d_in, const int* in_sizes, int n_in,
                              void* d_out, int out_size)
{
    const float* x    = (const float*)d_in[0];   // (64, 1024, 1024) f32
    const float* kern = (const float*)d_in[1];   // (16, 16) f32
    float* out = (float*)d_out;                  // (64, 1009, 1009) f32

    dim3 grid((OW + TILE_X - 1) / TILE_X,   // 11
              (OH + TILE_Y - 1) / TILE_Y,   // 16
              Bn);                          // 64
    conv2d_f32x2_kernel<<<grid, NTHREADS>>>(x, kern, out);
}

// round 5
// speedup vs baseline: 1.0015x; 1.0015x over previous
#include <cuda_runtime.h>
#include <cstdint>

// Problem constants
#define KH 16
#define KW 16
#define Bn 64
#define Hn 1024
#define Wn 1024
#define OH 1009
#define OW 1009

// Tiling: 256 threads = 8 col-groups x 32 row-slots.
// Each thread computes 4 consecutive output rows x 11 cols, as two f32x2
// row-pairs with pair distance D=2:  pair0=(y0,y0+2), pair1=(y0+1,y0+3).
// Main loop runs over INPUT row-pairs p (17 of them); each loaded window
// feeds pair0 (weight row p) and pair1 (weight row p-1) -> 2x window reuse.
#define CPT     11                  // cols per thread
#define TILE_X  88                  // 8 * CPT
#define TILE_Y  128                 // 32 slots * 4 rows
#define WINL    (CPT + KW - 1)      // 26 packed window values
#define TPITCH  106                 // >= TILE_X+15(=103); 106 % 8 == 2 -> conflict-free
#define TROWS   (TILE_Y + KH - 1)   // 143 input rows
#define NTHREADS 256
#define SMEM_T_BYTES (TROWS * TPITCH * 4)   // 60632 B (dynamic)

typedef unsigned long long ull;

// Packed dual-FMA (FFMA2): the 2x fp32-rate path on sm_103a.
__device__ __forceinline__ ull fma2(ull a, ull b, ull c) {
    ull d;
    asm("fma.rn.f32x2 %0, %1, %2, %3;" : "=l"(d) : "l"(a), "l"(b), "l"(c));
    return d;
}
__device__ __forceinline__ ull pack2(unsigned lo, unsigned hi) {
    ull d;
    asm("mov.b64 %0, {%1, %2};" : "=l"(d) : "r"(lo), "r"(hi));
    return d;
}

// Load a packed sliding window: win[j] = (rowLo[j], rowLo[j + 2*TPITCH]).
__device__ __forceinline__ void load_win(ull* win, const float* __restrict__ rowLo) {
    const float* rowHi = rowLo + 2 * TPITCH;
    #pragma unroll
    for (int j = 0; j < WINL; j++)
        win[j] = pack2(__float_as_uint(rowLo[j]), __float_as_uint(rowHi[j]));
}

// acc[j] += sum_kx win[j+kx] * w2[wrow*16+kx]   (all FFMA2, broadcast LDS.64 weights)
__device__ __forceinline__ void accum(ull* acc, const ull* win,
                                      const ull* __restrict__ wp64, int wrow) {
    #pragma unroll
    for (int kx = 0; kx < KW; kx++) {
        ull w2 = wp64[wrow * KW + kx];
        #pragma unroll
        for (int j = 0; j < CPT; j++)
            acc[j] = fma2(win[j + kx], w2, acc[j]);
    }
}

extern __shared__ float T[];   // [TROWS * TPITCH] input tile (dynamic, 60.6 KB)

__global__ __launch_bounds__(NTHREADS, 2)
void conv2d_f32x2_rr_kernel(const float* __restrict__ x,
                            const float* __restrict__ kern,
                            float* __restrict__ out)
{
    __shared__ float2 wdup[KH * KW];   // duplicated (w,w) weight pairs, 2 KB static

    const int tid = threadIdx.x;
    const int b   = blockIdx.z;
    const int gy0 = blockIdx.y * TILE_Y;
    const int gx0 = blockIdx.x * TILE_X;

    const float* __restrict__ xb = x + (size_t)b * (Hn * (size_t)Wn);

    // ---- weight pairs: 256 threads, 256 weights ----
    {
        float w = kern[tid];
        wdup[tid] = make_float2(w, w);
    }

    // ---- input tile fill (clamped; clamped values only feed discarded outputs) ----
    for (int idx = tid; idx < TROWS * TPITCH; idx += NTHREADS) {
        int r = idx / TPITCH;
        int c = idx - r * TPITCH;
        int gy = gy0 + r; if (gy > Hn - 1) gy = Hn - 1;
        int gx = gx0 + c; if (gx > Wn - 1) gx = Wn - 1;
        T[idx] = xb[(size_t)gy * Wn + gx];
    }
    __syncthreads();

    const int tx   = tid & 7;       // 0..7
    const int slot = tid >> 3;      // 0..31
    const int a0   = 4 * slot;      // local base output row (0..124)
    const int c0   = tx * CPT;      // 0..77

    ull acc0[CPT], acc1[CPT];
    #pragma unroll
    for (int j = 0; j < CPT; j++) { acc0[j] = 0ull; acc1[j] = 0ull; }

    const ull* __restrict__ wp64 = reinterpret_cast<const ull*>(wdup);
    const float* rowp = &T[a0 * TPITCH + c0];

    ull win[WINL];

    // p = 0: window pair (a0, a0+2) feeds only pair0 with weight row 0
    load_win(win, rowp);
    accum(acc0, win, wp64, 0);
    rowp += TPITCH;

    // p = 1..15: feeds pair0 (wrow=p) and pair1 (wrow=p-1)
    #pragma unroll 1   // keep body I-cache resident (~7 KB)
    for (int p = 1; p < KH; p++) {
        load_win(win, rowp);
        accum(acc0, win, wp64, p);
        accum(acc1, win, wp64, p - 1);
        rowp += TPITCH;
    }

    // p = 16: feeds only pair1 with weight row 15
    load_win(win, rowp);
    accum(acc1, win, wp64, KH - 1);

    // ---- epilogue: unpack pairs, guarded stores ----
    // acc0[j]: lo -> row a0,   hi -> row a0+2
    // acc1[j]: lo -> row a0+1, hi -> row a0+3
    float* __restrict__ outb = out + (size_t)b * (OH * (size_t)OW);
    const int oy = gy0 + a0;

    #pragma unroll
    for (int j = 0; j < CPT; j++) {
        int ox = gx0 + c0 + j;
        if (ox < OW) {
            float v0 = __uint_as_float((unsigned)(acc0[j] & 0xFFFFFFFFull));
            float v2 = __uint_as_float((unsigned)(acc0[j] >> 32));
            float v1 = __uint_as_float((unsigned)(acc1[j] & 0xFFFFFFFFull));
            float v3 = __uint_as_float((unsigned)(acc1[j] >> 32));
            if (oy     < OH) outb[(size_t)(oy    ) * OW + ox] = v0;
            if (oy + 1 < OH) outb[(size_t)(oy + 1) * OW + ox] = v1;
            if (oy + 2 < OH) outb[(size_t)(oy + 2) * OW + ox] = v2;
            if (oy + 3 < OH) outb[(size_t)(oy + 3) * OW + ox] = v3;
        }
    }
}

extern "C" void kernel_launch(void* const* d_in, const int* in_sizes, int n_in,
                              void* d_out, int out_size)
{
    const float* x    = (const float*)d_in[0];   // (64, 1024, 1024) f32
    const float* kern = (const float*)d_in[1];   // (16, 16) f32
    float* out = (float*)d_out;                  // (64, 1009, 1009) f32

    // Idempotent; executes immediately (not a stream op), capture-safe.
    cudaFuncSetAttribute(conv2d_f32x2_rr_kernel,
                         cudaFuncAttributeMaxDynamicSharedMemorySize, SMEM_T_BYTES);

    dim3 grid((OW + TILE_X - 1) / TILE_X,   // 12
              (OH + TILE_Y - 1) / TILE_Y,   // 8
              Bn);                          // 64
    conv2d_f32x2_rr_kernel<<<grid, NTHREADS, SMEM_T_BYTES>>>(x, kern, out);
}

// round 9
// speedup vs baseline: 1.4247x; 1.4226x over previous
#include <cuda_runtime.h>
#include <cuda_bf16.h>
#include <cstdint>

// ---------------- problem constants ----------------
#define KH 16
#define KW 16
#define Bn 64
#define Hn 1024
#define Wn 1024
#define OH 1009
#define OW 1009

// ---------------- tiling ----------------
// Block: 256 threads = 8 warps (4 in y, 2 in x). Block output tile 128y x 64x.
// Warp output tile 32y x 32x = 2 m-tiles x 2 q-groups x 2 n-halves of m16n8.
#define TILE_OY 128
#define TILE_OX 64
#define XROWS   143               // input rows needed: 128+15
#define XCOLS   80                // input cols needed: 64+15 (+1 spare)
#define XPITCH  88                // bf16 elems/row -> 176B; 176%128=48 -> ldmatrix conflict-free
#define XBYTES  (XROWS * XPITCH * 2)          // 25168
#define XH_OFF  0
#define XL_OFF  XBYTES
#define BW_OFF  (2 * XBYTES)                  // 50336 (16B aligned)
#define BW_PITCH 40               // elems per t-row -> 80B; 80%128=80 -> conflict-free
#define BW_BYTES (32 * 16 * BW_PITCH * 2)     // 40960
#define SMEM_DYN (BW_OFF + BW_BYTES)          // 91296
#define NTHREADS 256

// ---------------- PTX helpers (all sm_80-class, compile for compute_103) ----
__device__ __forceinline__ uint32_t smem_u32(const void* p) {
    uint32_t a;
    asm("{ .reg .u64 t; cvta.to.shared.u64 t, %1; cvt.u32.u64 %0, t; }" : "=r"(a) : "l"(p));
    return a;
}
__device__ __forceinline__ void ldsm_x4(uint32_t* r, uint32_t addr) {
    asm volatile("ldmatrix.sync.aligned.m8n8.x4.shared.b16 {%0,%1,%2,%3}, [%4];"
                 : "=r"(r[0]), "=r"(r[1]), "=r"(r[2]), "=r"(r[3]) : "r"(addr));
}
__device__ __forceinline__ void ldsm_x4_t(uint32_t* r, uint32_t addr) {
    asm volatile("ldmatrix.sync.aligned.m8n8.x4.trans.shared.b16 {%0,%1,%2,%3}, [%4];"
                 : "=r"(r[0]), "=r"(r[1]), "=r"(r[2]), "=r"(r[3]) : "r"(addr));
}
// D(16x8,f32) += A(16x16,bf16 row) * B(16x8,bf16 col)
__device__ __forceinline__ void mma_bf16(float* d, const uint32_t* a, const uint32_t* b) {
    asm volatile(
        "mma.sync.aligned.m16n8k16.row.col.f32.bf16.bf16.f32 "
        "{%0,%1,%2,%3}, {%4,%5,%6,%7}, {%8,%9}, {%0,%1,%2,%3};"
        : "+f"(d[0]), "+f"(d[1]), "+f"(d[2]), "+f"(d[3])
        : "r"(a[0]), "r"(a[1]), "r"(a[2]), "r"(a[3]), "r"(b[0]), "r"(b[1]));
}

extern __shared__ char dynsm[];

__global__ __launch_bounds__(NTHREADS, 2)
void conv2d_hmma_r7_kernel(const float* __restrict__ x,
                           const float* __restrict__ kern,
                           float* __restrict__ out)
{
    const int tid  = threadIdx.x;
    const int lane = tid & 31;
    const int wid  = tid >> 5;
    const int b    = blockIdx.z;
    const int y0   = blockIdx.y * TILE_OY;
    const int x0   = blockIdx.x * TILE_OX;

    __nv_bfloat16* XH = reinterpret_cast<__nv_bfloat16*>(dynsm + XH_OFF);
    __nv_bfloat16* XL = reinterpret_cast<__nv_bfloat16*>(dynsm + XL_OFF);
    __nv_bfloat16* BW = reinterpret_cast<__nv_bfloat16*>(dynsm + BW_OFF);

    // ---- fill X tile, split into bf16 hi/lo (clamped reads feed only discarded outputs) ----
    const float* __restrict__ xb = x + (size_t)b * (Hn * (size_t)Wn);
    for (int idx = tid; idx < XROWS * XCOLS; idx += NTHREADS) {
        int r = idx / XCOLS;
        int c = idx - r * XCOLS;
        int gy = y0 + r; if (gy > Hn - 1) gy = Hn - 1;
        int gx = x0 + c; if (gx > Wn - 1) gx = Wn - 1;
        float v = xb[(size_t)gy * Wn + gx];
        __nv_bfloat16 h = __float2bfloat16(v);
        __nv_bfloat16 l = __float2bfloat16(v - __bfloat162float(h));
        XH[r * XPITCH + c] = h;
        XL[r * XPITCH + c] = l;
    }

    // ---- build Toeplitz weight blocks: BW[ky][hl][t][v*16+n] (row pitch 40 elems) ----
    // Bv[t][n] = w_hl[ky, 16v + t - n] if 0 <= 16v+t-n < 16 else 0
    for (int idx = tid; idx < 16 * 2 * 16 * 32; idx += NTHREADS) {
        int ky  = idx >> 10;
        int rem = idx & 1023;
        int hl  = rem >> 9;
        int e   = rem & 511;
        int t   = e >> 5;
        int nn  = e & 31;
        int v   = nn >> 4;
        int n   = nn & 15;
        int kx  = 16 * v + t - n;
        float val = 0.0f;
        if (kx >= 0 && kx < KW) {
            float w = kern[ky * KW + kx];
            __nv_bfloat16 wh = __float2bfloat16(w);
            val = hl ? (w - __bfloat162float(wh)) : __bfloat162float(wh);
        }
        BW[((ky * 2 + hl) * 16 + t) * BW_PITCH + v * 16 + n] = __float2bfloat16(val);
    }
    __syncthreads();

    // ---- per-warp / per-lane constants ----
    const int wy  = wid >> 1;        // 0..3
    const int wx  = wid & 1;         // 0..1
    const int oyw = 32 * wy;         // warp row base within tile
    const int oxw = 32 * wx;         // warp col base within tile

    const int mat  = lane >> 3;      // ldmatrix matrix index 0..3
    const int rr   = lane & 7;
    const int grow = rr + 8 * (mat & 1);
    const int g8   = (mat >> 1) * 8;
    const uint32_t aoff_lane = (uint32_t)(grow * XPITCH + g8) * 2;
    const uint32_t boff_lane = (uint32_t)(grow * BW_PITCH + g8) * 2;
    const uint32_t sm_base = smem_u32(dynsm);

    float acc[2][2][2][4];           // [my][q][nh][4]
    #pragma unroll
    for (int i = 0; i < 2; i++)
        #pragma unroll
        for (int j = 0; j < 2; j++)
            #pragma unroll
            for (int k = 0; k < 2; k++)
                #pragma unroll
                for (int l = 0; l < 4; l++) acc[i][j][k][l] = 0.0f;

    #pragma unroll 1
    for (int ky = 0; ky < KH; ky++) {
        // A fragments: 2 m-tiles x 3 col-panels, hi & lo
        uint32_t Ah[2][3][4], Al[2][3][4];
        #pragma unroll
        for (int my = 0; my < 2; my++) {
            #pragma unroll
            for (int p = 0; p < 3; p++) {
                uint32_t o = (uint32_t)((oyw + ky + 16 * my) * XPITCH + oxw + 16 * p) * 2
                           + aoff_lane;
                ldsm_x4(Ah[my][p], sm_base + XH_OFF + o);
                ldsm_x4(Al[my][p], sm_base + XL_OFF + o);
            }
        }
        // B fragments: [v][4 regs] (regs 0,1 = n-half 0 k0/k1; regs 2,3 = n-half 1)
        uint32_t Bh[2][4], Bl[2][4];
        #pragma unroll
        for (int v = 0; v < 2; v++) {
            uint32_t boh = (uint32_t)((ky * 2 + 0) * 16 * BW_PITCH * 2) + v * 32 + boff_lane;
            uint32_t bol = (uint32_t)((ky * 2 + 1) * 16 * BW_PITCH * 2) + v * 32 + boff_lane;
            ldsm_x4_t(Bh[v], sm_base + BW_OFF + boh);
            ldsm_x4_t(Bl[v], sm_base + BW_OFF + bol);
        }
        // 48 MMAs: my x q x v x {XhWh, XlWh, XhWl} x nhalf
        #pragma unroll
        for (int my = 0; my < 2; my++) {
            #pragma unroll
            for (int q = 0; q < 2; q++) {
                #pragma unroll
                for (int v = 0; v < 2; v++) {
                    const uint32_t* ah = Ah[my][q + v];
                    const uint32_t* al = Al[my][q + v];
                    mma_bf16(acc[my][q][0], ah, &Bh[v][0]);
                    mma_bf16(acc[my][q][1], ah, &Bh[v][2]);
                    mma_bf16(acc[my][q][0], al, &Bh[v][0]);
                    mma_bf16(acc[my][q][1], al, &Bh[v][2]);
                    mma_bf16(acc[my][q][0], ah, &Bl[v][0]);
                    mma_bf16(acc[my][q][1], ah, &Bl[v][2]);
                }
            }
        }
    }

    // ---- epilogue: D frag (m16n8): d0=(g,c) d1=(g,c+1) d2=(g+8,c) d3=(g+8,c+1) ----
    float* __restrict__ outb = out + (size_t)b * (OH * (size_t)OW);
    const int g  = lane >> 2;
    const int c2 = (lane & 3) * 2;
    #pragma unroll
    for (int my = 0; my < 2; my++) {
        #pragma unroll
        for (int q = 0; q < 2; q++) {
            #pragma unroll
            for (int nh = 0; nh < 2; nh++) {
                const float* d = acc[my][q][nh];
                int row = y0 + oyw + 16 * my + g;
                int col = x0 + oxw + 16 * q + 8 * nh + c2;
                if (col < OW) {
                    bool c1 = (col + 1 < OW);
                    if (row < OH) {
                        float* po = outb + (size_t)row * OW + col;
                        po[0] = d[0];
                        if (c1) po[1] = d[1];
                    }
                    if (row + 8 < OH) {
                        float* po = outb + (size_t)(row + 8) * OW + col;
                        po[0] = d[2];
                        if (c1) po[1] = d[3];
                    }
                }
            }
        }
    }
}

extern "C" void kernel_launch(void* const* d_in, const int* in_sizes, int n_in,
                              void* d_out, int out_size)
{
    const float* x    = (const float*)d_in[0];   // (64, 1024, 1024) f32
    const float* kern = (const float*)d_in[1];   // (16, 16) f32
    float* out = (float*)d_out;                  // (64, 1009, 1009) f32

    cudaFuncSetAttribute(conv2d_hmma_r7_kernel,
                         cudaFuncAttributeMaxDynamicSharedMemorySize, SMEM_DYN);

    dim3 grid((OW + TILE_OX - 1) / TILE_OX,   // 16
              (OH + TILE_OY - 1) / TILE_OY,   // 8
              Bn);                            // 64
    conv2d_hmma_r7_kernel<<<grid, NTHREADS, SMEM_DYN>>>(x, kern, out);
}

// round 10
// speedup vs baseline: 1.7487x; 1.2274x over previous
#include <cuda_runtime.h>
#include <cuda_bf16.h>
#include <cstdint>

// ---------------- problem constants ----------------
#define KH 16
#define KW 16
#define Bn 64
#define Hn 1024
#define Wn 1024
#define OH 1009
#define OW 1009

// ---------------- tiling ----------------
// Block: 256 threads = 8 warps (4 in y, 2 in x). Block output tile 64y x 64x.
// Warp output tile 16y x 32x = 2 q-groups x 2 n-halves of m16n8 (single m-tile).
#define TILE_OY 64
#define TILE_OX 64
#define XROWS   79                // input rows needed: 64+15
#define XCOLS   80                // input cols needed: 64+15 (+1 spare)
#define XPITCH  88                // bf16/row -> 176B; slot walk mod 128 conflict-free
#define XBYTES  (XROWS * XPITCH * 2)          // 13904
#define XH_OFF  0
#define XL_OFF  XBYTES                        // 13904
#define BW_OFF  (2 * XBYTES)                  // 27808 (16B aligned)
#define BW_PITCH 40               // 80B rows; 5-slot walk mod 128 conflict-free
#define BW_ROWS  (16 * 2 * 16)    // ky * hl * t = 512
#define BW_BYTES (BW_ROWS * BW_PITCH * 2)     // 40960
#define SMEM_DYN (BW_OFF + BW_BYTES)          // 68768 -> 3 CTAs/SM
#define NTHREADS 256

// Precomputed Toeplitz-weight smem image (exact byte layout), built once by a
// tiny pre-kernel into device scratch, then block-copied from (hot) L2.
__device__ uint4 g_bw[BW_BYTES / 16];         // 2560 x uint4

// ---------------- PTX helpers (sm_80-class; compile for compute_103) ----
__device__ __forceinline__ uint32_t smem_u32(const void* p) {
    uint32_t a;
    asm("{ .reg .u64 t; cvta.to.shared.u64 t, %1; cvt.u32.u64 %0, t; }" : "=r"(a) : "l"(p));
    return a;
}
__device__ __forceinline__ void ldsm_x4(uint32_t* r, uint32_t addr) {
    asm volatile("ldmatrix.sync.aligned.m8n8.x4.shared.b16 {%0,%1,%2,%3}, [%4];"
                 : "=r"(r[0]), "=r"(r[1]), "=r"(r[2]), "=r"(r[3]) : "r"(addr));
}
__device__ __forceinline__ void ldsm_x4_t(uint32_t* r, uint32_t addr) {
    asm volatile("ldmatrix.sync.aligned.m8n8.x4.trans.shared.b16 {%0,%1,%2,%3}, [%4];"
                 : "=r"(r[0]), "=r"(r[1]), "=r"(r[2]), "=r"(r[3]) : "r"(addr));
}
// D(16x8,f32) += A(16x16,bf16 row) * B(16x8,bf16 col)
__device__ __forceinline__ void mma_bf16(float* d, const uint32_t* a, const uint32_t* b) {
    asm volatile(
        "mma.sync.aligned.m16n8k16.row.col.f32.bf16.bf16.f32 "
        "{%0,%1,%2,%3}, {%4,%5,%6,%7}, {%8,%9}, {%0,%1,%2,%3};"
        : "+f"(d[0]), "+f"(d[1]), "+f"(d[2]), "+f"(d[3])
        : "r"(a[0]), "r"(a[1]), "r"(a[2]), "r"(a[3]), "r"(b[0]), "r"(b[1]));
}

// ---------------- pre-kernel: build Toeplitz weight image ----------------
// Row r = (ky*2 + hl)*16 + t ; col c = v*16 + n (c >= 32 is zero padding)
// Bv_hl[t][n] = w_hl[ky, 16v + t - n] if in range else 0
__global__ void build_bw_kernel(const float* __restrict__ kern) {
    int idx = blockIdx.x * blockDim.x + threadIdx.x;   // over BW_ROWS * BW_PITCH
    if (idx >= BW_ROWS * BW_PITCH) return;
    int r  = idx / BW_PITCH;
    int c  = idx - r * BW_PITCH;
    int ky = r >> 5;
    int hl = (r >> 4) & 1;
    int t  = r & 15;
    float val = 0.0f;
    if (c < 32) {
        int v  = c >> 4;
        int n  = c & 15;
        int kx = 16 * v + t - n;
        if (kx >= 0 && kx < KW) {
            float w = kern[ky * KW + kx];
            __nv_bfloat16 wh = __float2bfloat16(w);
            val = hl ? (w - __bfloat162float(wh)) : __bfloat162float(wh);
        }
    }
    reinterpret_cast<__nv_bfloat16*>(g_bw)[idx] = __float2bfloat16(val);
}

extern __shared__ char dynsm[];

__global__ __launch_bounds__(NTHREADS, 3)
void conv2d_hmma_r10_kernel(const float* __restrict__ x,
                            float* __restrict__ out)
{
    const int tid  = threadIdx.x;
    const int lane = tid & 31;
    const int wid  = tid >> 5;
    const int b    = blockIdx.z;
    const int y0   = blockIdx.y * TILE_OY;
    const int x0   = blockIdx.x * TILE_OX;

    __nv_bfloat16* XH = reinterpret_cast<__nv_bfloat16*>(dynsm + XH_OFF);
    __nv_bfloat16* XL = reinterpret_cast<__nv_bfloat16*>(dynsm + XL_OFF);

    // ---- copy Toeplitz weight image from device scratch (L2-hot) ----
    {
        uint4* dstq = reinterpret_cast<uint4*>(dynsm + BW_OFF);
        #pragma unroll
        for (int i = 0; i < BW_BYTES / 16 / NTHREADS; i++)      // 10 iters
            dstq[tid + i * NTHREADS] = g_bw[tid + i * NTHREADS];
    }

    // ---- fill X tile, split into bf16 hi/lo (clamped reads feed only discarded outputs) ----
    const float* __restrict__ xb = x + (size_t)b * (Hn * (size_t)Wn);
    for (int idx = tid; idx < XROWS * XCOLS; idx += NTHREADS) {
        int r = idx / XCOLS;
        int c = idx - r * XCOLS;
        int gy = y0 + r; if (gy > Hn - 1) gy = Hn - 1;
        int gx = x0 + c; if (gx > Wn - 1) gx = Wn - 1;
        float v = xb[(size_t)gy * Wn + gx];
        __nv_bfloat16 h = __float2bfloat16(v);
        __nv_bfloat16 l = __float2bfloat16(v - __bfloat162float(h));
        XH[r * XPITCH + c] = h;
        XL[r * XPITCH + c] = l;
    }
    __syncthreads();

    // ---- per-warp / per-lane constants ----
    const int wy  = wid >> 1;        // 0..3
    const int wx  = wid & 1;         // 0..1
    const int oyw = 16 * wy;         // warp row base within tile
    const int oxw = 32 * wx;         // warp col base within tile

    const int mat  = lane >> 3;      // ldmatrix matrix index 0..3
    const int rr   = lane & 7;
    const int grow = rr + 8 * (mat & 1);
    const int g8   = (mat >> 1) * 8;
    const uint32_t aoff_lane = (uint32_t)(grow * XPITCH + g8) * 2;
    const uint32_t boff_lane = (uint32_t)(grow * BW_PITCH + g8) * 2;
    const uint32_t sm_base = smem_u32(dynsm);

    float acc[2][2][4];              // [q][nh][4]
    #pragma unroll
    for (int j = 0; j < 2; j++)
        #pragma unroll
        for (int k = 0; k < 2; k++)
            #pragma unroll
            for (int l = 0; l < 4; l++) acc[j][k][l] = 0.0f;

    #pragma unroll 1
    for (int ky = 0; ky < KH; ky++) {
        // A fragments: 3 col-panels, hi & lo
        uint32_t Ah[3][4], Al[3][4];
        #pragma unroll
        for (int p = 0; p < 3; p++) {
            uint32_t o = (uint32_t)((oyw + ky) * XPITCH + oxw + 16 * p) * 2 + aoff_lane;
            ldsm_x4(Ah[p], sm_base + XH_OFF + o);
            ldsm_x4(Al[p], sm_base + XL_OFF + o);
        }
        // B fragments: [v][4 regs]: regs 0,1 = n-half 0 (k0/k1); regs 2,3 = n-half 1
        uint32_t Bh[2][4], Bl[2][4];
        #pragma unroll
        for (int v = 0; v < 2; v++) {
            uint32_t boh = (uint32_t)((ky * 2 + 0) * 16 * BW_PITCH * 2) + v * 32 + boff_lane;
            uint32_t bol = (uint32_t)((ky * 2 + 1) * 16 * BW_PITCH * 2) + v * 32 + boff_lane;
            ldsm_x4_t(Bh[v], sm_base + BW_OFF + boh);
            ldsm_x4_t(Bl[v], sm_base + BW_OFF + bol);
        }
        // 24 MMAs: q x v x {XhWh, XlWh, XhWl} x nhalf
        #pragma unroll
        for (int q = 0; q < 2; q++) {
            #pragma unroll
            for (int v = 0; v < 2; v++) {
                const uint32_t* ah = Ah[q + v];
                const uint32_t* al = Al[q + v];
                mma_bf16(acc[q][0], ah, &Bh[v][0]);
                mma_bf16(acc[q][1], ah, &Bh[v][2]);
                mma_bf16(acc[q][0], al, &Bh[v][0]);
                mma_bf16(acc[q][1], al, &Bh[v][2]);
                mma_bf16(acc[q][0], ah, &Bl[v][0]);
                mma_bf16(acc[q][1], ah, &Bl[v][2]);
            }
        }
    }

    // ---- epilogue: D frag (m16n8): d0=(g,c) d1=(g,c+1) d2=(g+8,c) d3=(g+8,c+1) ----
    float* __restrict__ outb = out + (size_t)b * (OH * (size_t)OW);
    const int g  = lane >> 2;
    const int c2 = (lane & 3) * 2;
    #pragma unroll
    for (int q = 0; q < 2; q++) {
        #pragma unroll
        for (int nh = 0; nh < 2; nh++) {
            const float* d = acc[q][nh];
            int row = y0 + oyw + g;
            int col = x0 + oxw + 16 * q + 8 * nh + c2;
            if (col < OW) {
                bool c1 = (col + 1 < OW);
                if (row < OH) {
                    float* po = outb + (size_t)row * OW + col;
                    po[0] = d[0];
                    if (c1) po[1] = d[1];
                }
                if (row + 8 < OH) {
                    float* po = outb + (size_t)(row + 8) * OW + col;
                    po[0] = d[2];
                    if (c1) po[1] = d[3];
                }
            }
        }
    }
}

extern "C" void kernel_launch(void* const* d_in, const int* in_sizes, int n_in,
                              void* d_out, int out_size)
{
    const float* x    = (const float*)d_in[0];   // (64, 1024, 1024) f32
    const float* kern = (const float*)d_in[1];   // (16, 16) f32
    float* out = (float*)d_out;                  // (64, 1009, 1009) f32

    // Build the Toeplitz weight image (depends only on kern; deterministic).
    build_bw_kernel<<<(BW_ROWS * BW_PITCH + 255) / 256, 256>>>(kern);

    cudaFuncSetAttribute(conv2d_hmma_r10_kernel,
                         cudaFuncAttributeMaxDynamicSharedMemorySize, SMEM_DYN);

    dim3 grid((OW + TILE_OX - 1) / TILE_OX,   // 16
              (OH + TILE_OY - 1) / TILE_OY,   // 16
              Bn);                            // 64
    conv2d_hmma_r10_kernel<<<grid, NTHREADS, SMEM_DYN>>>(x, out);
}

// round 13
// speedup vs baseline: 2.3561x; 1.3473x over previous
#include <cuda_runtime.h>
#include <cuda_fp16.h>
#include <cstdint>

// ---------------- problem constants ----------------
#define KH 16
#define KW 16
#define Bn 64
#define Hn 1024
#define Wn 1024
#define OH 1009
#define OW 1009

// ---------------- tiling ----------------
// Block: 256 threads = 8 warps (4 in y, 2 in x). Block output tile 64y x 64x.
// Warp output tile 16y x 32x = 2 q-groups x 2 n-halves of m16n8.
// Precision: X in single fp16 (11-bit mantissa, rel err ~2^-12); W split into
// fp16 hi+lo (W exact to ~2^-24). 2 MMA passes: X*Wh + X*Wl.
#define TILE_OY 64
#define TILE_OX 64
#define XROWS   79                // input rows needed: 64+15
#define XCOLS   80                // input cols needed: 64+15 (+1 spare)
#define XPITCH  88                // fp16/row -> 176B; ldmatrix conflict-free
#define XBYTES  (XROWS * XPITCH * 2)          // 13904
#define X_OFF   0
#define BW_OFF  XBYTES                        // 13904 (16B aligned)
#define BW_PITCH 40               // 80B rows; conflict-free for ldmatrix.trans
#define BW_ROWS  (16 * 2 * 16)    // ky * hl * t = 512
#define BW_BYTES (BW_ROWS * BW_PITCH * 2)     // 40960
#define SMEM_DYN (BW_OFF + BW_BYTES)          // 54864 -> 4 CTAs/SM
#define NTHREADS 256

// Precomputed Toeplitz-weight smem image (exact byte layout), built by a tiny
// pre-kernel into device scratch, then block-copied from (hot) L2.
__device__ uint4 g_bw[BW_BYTES / 16];         // 2560 x uint4

// ---------------- PTX helpers (sm_80-class; compile for compute_103) ----
__device__ __forceinline__ uint32_t smem_u32(const void* p) {
    uint32_t a;
    asm("{ .reg .u64 t; cvta.to.shared.u64 t, %1; cvt.u32.u64 %0, t; }" : "=r"(a) : "l"(p));
    return a;
}
__device__ __forceinline__ void ldsm_x4(uint32_t* r, uint32_t addr) {
    asm volatile("ldmatrix.sync.aligned.m8n8.x4.shared.b16 {%0,%1,%2,%3}, [%4];"
                 : "=r"(r[0]), "=r"(r[1]), "=r"(r[2]), "=r"(r[3]) : "r"(addr));
}
__device__ __forceinline__ void ldsm_x4_t(uint32_t* r, uint32_t addr) {
    asm volatile("ldmatrix.sync.aligned.m8n8.x4.trans.shared.b16 {%0,%1,%2,%3}, [%4];"
                 : "=r"(r[0]), "=r"(r[1]), "=r"(r[2]), "=r"(r[3]) : "r"(addr));
}
// D(16x8,f32) += A(16x16,f16 row) * B(16x8,f16 col)
__device__ __forceinline__ void mma_f16(float* d, const uint32_t* a, const uint32_t* b) {
    asm volatile(
        "mma.sync.aligned.m16n8k16.row.col.f32.f16.f16.f32 "
        "{%0,%1,%2,%3}, {%4,%5,%6,%7}, {%8,%9}, {%0,%1,%2,%3};"
        : "+f"(d[0]), "+f"(d[1]), "+f"(d[2]), "+f"(d[3])
        : "r"(a[0]), "r"(a[1]), "r"(a[2]), "r"(a[3]), "r"(b[0]), "r"(b[1]));
}

// ---------------- pre-kernel: build Toeplitz weight image (fp16 hi/lo) -----
// Row r = (ky*2 + hl)*16 + t ; col c = v*16 + n (c >= 32 is zero padding)
// Bv_hl[t][n] = whl[ky, 16v + t - n] if in range else 0
__global__ void build_bw_kernel(const float* __restrict__ kern) {
    int idx = blockIdx.x * blockDim.x + threadIdx.x;   // over BW_ROWS * BW_PITCH
    if (idx >= BW_ROWS * BW_PITCH) return;
    int r  = idx / BW_PITCH;
    int c  = idx - r * BW_PITCH;
    int ky = r >> 5;
    int hl = (r >> 4) & 1;
    int t  = r & 15;
    __half val = __float2half_rn(0.0f);
    if (c < 32) {
        int v  = c >> 4;
        int n  = c & 15;
        int kx = 16 * v + t - n;
        if (kx >= 0 && kx < KW) {
            float w = kern[ky * KW + kx];
            __half wh = __float2half_rn(w);
            val = hl ? __float2half_rn(w - __half2float(wh)) : wh;
        }
    }
    reinterpret_cast<__half*>(g_bw)[idx] = val;
}

extern __shared__ char dynsm[];

__global__ __launch_bounds__(NTHREADS, 4)
void conv2d_hmma_r11_kernel(const float* __restrict__ x,
                            float* __restrict__ out)
{
    const int tid  = threadIdx.x;
    const int lane = tid & 31;
    const int wid  = tid >> 5;
    const int b    = blockIdx.z;
    const int y0   = blockIdx.y * TILE_OY;
    const int x0   = blockIdx.x * TILE_OX;

    __half* X = reinterpret_cast<__half*>(dynsm + X_OFF);

    // ---- copy Toeplitz weight image from device scratch (L2-hot) ----
    {
        uint4* dstq = reinterpret_cast<uint4*>(dynsm + BW_OFF);
        #pragma unroll
        for (int i = 0; i < BW_BYTES / 16 / NTHREADS; i++)      // 10 iters
            dstq[tid + i * NTHREADS] = g_bw[tid + i * NTHREADS];
    }

    // ---- fill X tile as fp16 (clamped reads feed only discarded outputs) ----
    const float* __restrict__ xb = x + (size_t)b * (Hn * (size_t)Wn);
    for (int idx = tid; idx < XROWS * XCOLS; idx += NTHREADS) {
        int r = idx / XCOLS;
        int c = idx - r * XCOLS;
        int gy = y0 + r; if (gy > Hn - 1) gy = Hn - 1;
        int gx = x0 + c; if (gx > Wn - 1) gx = Wn - 1;
        X[r * XPITCH + c] = __float2half_rn(xb[(size_t)gy * Wn + gx]);
    }
    __syncthreads();

    // ---- per-warp / per-lane constants ----
    const int wy  = wid >> 1;        // 0..3
    const int wx  = wid & 1;         // 0..1
    const int oyw = 16 * wy;         // warp row base within tile
    const int oxw = 32 * wx;         // warp col base within tile

    const int mat  = lane >> 3;      // ldmatrix matrix index 0..3
    const int rr   = lane & 7;
    const int grow = rr + 8 * (mat & 1);
    const int g8   = (mat >> 1) * 8;
    const uint32_t aoff_lane = (uint32_t)(grow * XPITCH + g8) * 2;
    const uint32_t boff_lane = (uint32_t)(grow * BW_PITCH + g8) * 2;
    const uint32_t sm_base = smem_u32(dynsm);

    float acc[2][2][4];              // [q][nh][4]
    #pragma unroll
    for (int j = 0; j < 2; j++)
        #pragma unroll
        for (int k = 0; k < 2; k++)
            #pragma unroll
            for (int l = 0; l < 4; l++) acc[j][k][l] = 0.0f;

    #pragma unroll 1
    for (int ky = 0; ky < KH; ky++) {
        // A fragments: 3 col-panels (single fp16 X)
        uint32_t A[3][4];
        #pragma unroll
        for (int p = 0; p < 3; p++) {
            uint32_t o = (uint32_t)((oyw + ky) * XPITCH + oxw + 16 * p) * 2 + aoff_lane;
            ldsm_x4(A[p], sm_base + X_OFF + o);
        }
        // B fragments: [v][4 regs]: regs 0,1 = n-half 0 (k0/k1); regs 2,3 = n-half 1
        uint32_t Bh[2][4], Bl[2][4];
        #pragma unroll
        for (int v = 0; v < 2; v++) {
            uint32_t boh = (uint32_t)((ky * 2 + 0) * 16 * BW_PITCH * 2) + v * 32 + boff_lane;
            uint32_t bol = (uint32_t)((ky * 2 + 1) * 16 * BW_PITCH * 2) + v * 32 + boff_lane;
            ldsm_x4_t(Bh[v], sm_base + BW_OFF + boh);
            ldsm_x4_t(Bl[v], sm_base + BW_OFF + bol);
        }
        // 16 MMAs: q x v x {Wh, Wl} x nhalf
        #pragma unroll
        for (int q = 0; q < 2; q++) {
            #pragma unroll
            for (int v = 0; v < 2; v++) {
                const uint32_t* a = A[q + v];
                mma_f16(acc[q][0], a, &Bh[v][0]);
                mma_f16(acc[q][1], a, &Bh[v][2]);
                mma_f16(acc[q][0], a, &Bl[v][0]);
                mma_f16(acc[q][1], a, &Bl[v][2]);
            }
        }
    }

    // ---- epilogue: D frag (m16n8): d0=(g,c) d1=(g,c+1) d2=(g+8,c) d3=(g+8,c+1) ----
    float* __restrict__ outb = out + (size_t)b * (OH * (size_t)OW);
    const int g  = lane >> 2;
    const int c2 = (lane & 3) * 2;
    #pragma unroll
    for (int q = 0; q < 2; q++) {
        #pragma unroll
        for (int nh = 0; nh < 2; nh++) {
            const float* d = acc[q][nh];
            int row = y0 + oyw + g;
            int col = x0 + oxw + 16 * q + 8 * nh + c2;
            if (col < OW) {
                bool c1 = (col + 1 < OW);
                if (row < OH) {
                    float* po = outb + (size_t)row * OW + col;
                    po[0] = d[0];
                    if (c1) po[1] = d[1];
                }
                if (row + 8 < OH) {
                    float* po = outb + (size_t)(row + 8) * OW + col;
                    po[0] = d[2];
                    if (c1) po[1] = d[3];
                }
            }
        }
    }
}

extern "C" void kernel_launch(void* const* d_in, const int* in_sizes, int n_in,
                              void* d_out, int out_size)
{
    const float* x    = (const float*)d_in[0];   // (64, 1024, 1024) f32
    const float* kern = (const float*)d_in[1];   // (16, 16) f32
    float* out = (float*)d_out;                  // (64, 1009, 1009) f32

    // Build the Toeplitz weight image (depends only on kern; deterministic).
    build_bw_kernel<<<(BW_ROWS * BW_PITCH + 255) / 256, 256>>>(kern);

    cudaFuncSetAttribute(conv2d_hmma_r11_kernel,
                         cudaFuncAttributeMaxDynamicSharedMemorySize, SMEM_DYN);

    dim3 grid((OW + TILE_OX - 1) / TILE_OX,   // 16
              (OH + TILE_OY - 1) / TILE_OY,   // 16
              Bn);                            // 64
    conv2d_hmma_r11_kernel<<<grid, NTHREADS, SMEM_DYN>>>(x, out);
}

// round 14
// speedup vs baseline: 2.9521x; 1.2529x over previous
#include <cuda_runtime.h>
#include <cuda_fp16.h>
#include <cstdint>

// ---------------- problem constants ----------------
#define KH 16
#define KW 16
#define Bn 64
#define Hn 1024
#define Wn 1024
#define OH 1009
#define OW 1009

// ---------------- tiling ----------------
// Block: 256 threads = 8 warps stacked in y. Block output tile 128y x 64x.
// Warp output tile 16y x 64x = 4 q-groups x 2 n-halves of m16n8.
// Precision: X and W both in plain fp16 (single MMA pass). Measured error
// budget: X-quant ~2.1e-4 + W-quant ~2e-4 (independent) => ~2.9e-4 << 1e-3.
#define TILE_OY 128
#define TILE_OX 64
#define XROWS   143               // input rows needed: 128+15
#define XCOLS   80                // input cols needed: 64+15 (+1 spare)
#define XPITCH  88                // fp16/row -> 176B; ldmatrix conflict-free
#define XBYTES  (XROWS * XPITCH * 2)          // 25168
#define X_OFF   0
#define BW_OFF  XBYTES                        // 25168 (16B aligned)
#define BW_PITCH 40               // 80B rows; conflict-free for ldmatrix.trans
#define BW_ROWS  (16 * 16)        // ky * t = 256
#define BW_BYTES (BW_ROWS * BW_PITCH * 2)     // 20480
#define SMEM_DYN (BW_OFF + BW_BYTES)          // 45648 -> 3 CTAs/SM (reg-capped)
#define NTHREADS 256

// Precomputed Toeplitz-weight smem image (exact byte layout), built by a tiny
// pre-kernel into device scratch, then block-copied from (hot) L2.
__device__ uint4 g_bw[BW_BYTES / 16];         // 1280 x uint4

// ---------------- PTX helpers (sm_80-class; compile for compute_103) ----
__device__ __forceinline__ uint32_t smem_u32(const void* p) {
    uint32_t a;
    asm("{ .reg .u64 t; cvta.to.shared.u64 t, %1; cvt.u32.u64 %0, t; }" : "=r"(a) : "l"(p));
    return a;
}
__device__ __forceinline__ void ldsm_x4(uint32_t* r, uint32_t addr) {
    asm volatile("ldmatrix.sync.aligned.m8n8.x4.shared.b16 {%0,%1,%2,%3}, [%4];"
                 : "=r"(r[0]), "=r"(r[1]), "=r"(r[2]), "=r"(r[3]) : "r"(addr));
}
__device__ __forceinline__ void ldsm_x4_t(uint32_t* r, uint32_t addr) {
    asm volatile("ldmatrix.sync.aligned.m8n8.x4.trans.shared.b16 {%0,%1,%2,%3}, [%4];"
                 : "=r"(r[0]), "=r"(r[1]), "=r"(r[2]), "=r"(r[3]) : "r"(addr));
}
// D(16x8,f32) += A(16x16,f16 row) * B(16x8,f16 col)
__device__ __forceinline__ void mma_f16(float* d, const uint32_t* a, const uint32_t* b) {
    asm volatile(
        "mma.sync.aligned.m16n8k16.row.col.f32.f16.f16.f32 "
        "{%0,%1,%2,%3}, {%4,%5,%6,%7}, {%8,%9}, {%0,%1,%2,%3};"
        : "+f"(d[0]), "+f"(d[1]), "+f"(d[2]), "+f"(d[3])
        : "r"(a[0]), "r"(a[1]), "r"(a[2]), "r"(a[3]), "r"(b[0]), "r"(b[1]));
}

// ---------------- pre-kernel: build Toeplitz weight image (plain fp16) -----
// Row r = ky*16 + t ; col c = v*16 + n (c >= 32 is zero padding)
// Bv[t][n] = w[ky, 16v + t - n] if in range else 0
__global__ void build_bw_kernel(const float* __restrict__ kern) {
    int idx = blockIdx.x * blockDim.x + threadIdx.x;   // over BW_ROWS * BW_PITCH
    if (idx >= BW_ROWS * BW_PITCH) return;
    int r  = idx / BW_PITCH;
    int c  = idx - r * BW_PITCH;
    int ky = r >> 4;
    int t  = r & 15;
    __half val = __float2half_rn(0.0f);
    if (c < 32) {
        int v  = c >> 4;
        int n  = c & 15;
        int kx = 16 * v + t - n;
        if (kx >= 0 && kx < KW)
            val = __float2half_rn(kern[ky * KW + kx]);
    }
    reinterpret_cast<__half*>(g_bw)[idx] = val;
}

extern __shared__ char dynsm[];

__global__ __launch_bounds__(NTHREADS, 3)
void conv2d_hmma_r14_kernel(const float* __restrict__ x,
                            float* __restrict__ out)
{
    const int tid  = threadIdx.x;
    const int lane = tid & 31;
    const int wid  = tid >> 5;
    const int b    = blockIdx.z;
    const int y0   = blockIdx.y * TILE_OY;
    const int x0   = blockIdx.x * TILE_OX;

    __half* X = reinterpret_cast<__half*>(dynsm + X_OFF);

    // ---- copy Toeplitz weight image from device scratch (L2-hot) ----
    {
        uint4* dstq = reinterpret_cast<uint4*>(dynsm + BW_OFF);
        #pragma unroll
        for (int i = 0; i < BW_BYTES / 16 / NTHREADS; i++)      // 5 iters
            dstq[tid + i * NTHREADS] = g_bw[tid + i * NTHREADS];
    }

    // ---- fill X tile as fp16 (clamped reads feed only discarded outputs) ----
    const float* __restrict__ xb = x + (size_t)b * (Hn * (size_t)Wn);
    for (int idx = tid; idx < XROWS * XCOLS; idx += NTHREADS) {
        int r = idx / XCOLS;
        int c = idx - r * XCOLS;
        int gy = y0 + r; if (gy > Hn - 1) gy = Hn - 1;
        int gx = x0 + c; if (gx > Wn - 1) gx = Wn - 1;
        X[r * XPITCH + c] = __float2half_rn(xb[(size_t)gy * Wn + gx]);
    }
    __syncthreads();

    // ---- per-warp / per-lane constants ----
    const int oyw = 16 * wid;        // warp row base within tile (0..112)

    const int mat  = lane >> 3;      // ldmatrix matrix index 0..3
    const int rr   = lane & 7;
    const int grow = rr + 8 * (mat & 1);
    const int g8   = (mat >> 1) * 8;
    const uint32_t aoff_lane = (uint32_t)(grow * XPITCH + g8) * 2;
    const uint32_t boff_lane = (uint32_t)(grow * BW_PITCH + g8) * 2;
    const uint32_t sm_base = smem_u32(dynsm);

    float acc[4][2][4];              // [q][nh][4]
    #pragma unroll
    for (int j = 0; j < 4; j++)
        #pragma unroll
        for (int k = 0; k < 2; k++)
            #pragma unroll
            for (int l = 0; l < 4; l++) acc[j][k][l] = 0.0f;

    #pragma unroll 1
    for (int ky = 0; ky < KH; ky++) {
        // A fragments: 5 col-panels (16 cols each, covering 80 input cols)
        uint32_t A[5][4];
        #pragma unroll
        for (int p = 0; p < 5; p++) {
            uint32_t o = (uint32_t)((oyw + ky) * XPITCH + 16 * p) * 2 + aoff_lane;
            ldsm_x4(A[p], sm_base + X_OFF + o);
        }
        // B fragments: [v][4 regs]: regs 0,1 = n-half 0 (k0/k1); regs 2,3 = n-half 1
        uint32_t Bv[2][4];
        #pragma unroll
        for (int v = 0; v < 2; v++) {
            uint32_t bo = (uint32_t)(ky * 16 * BW_PITCH * 2) + v * 32 + boff_lane;
            ldsm_x4_t(Bv[v], sm_base + BW_OFF + bo);
        }
        // 16 MMAs: q x v x nhalf
        #pragma unroll
        for (int q = 0; q < 4; q++) {
            #pragma unroll
            for (int v = 0; v < 2; v++) {
                const uint32_t* a = A[q + v];
                mma_f16(acc[q][0], a, &Bv[v][0]);
                mma_f16(acc[q][1], a, &Bv[v][2]);
            }
        }
    }

    // ---- epilogue: D frag (m16n8): d0=(g,c) d1=(g,c+1) d2=(g+8,c) d3=(g+8,c+1) ----
    float* __restrict__ outb = out + (size_t)b * (OH * (size_t)OW);
    const int g  = lane >> 2;
    const int c2 = (lane & 3) * 2;
    #pragma unroll
    for (int q = 0; q < 4; q++) {
        #pragma unroll
        for (int nh = 0; nh < 2; nh++) {
            const float* d = acc[q][nh];
            int row = y0 + oyw + g;
            int col = x0 + 16 * q + 8 * nh + c2;
            if (col < OW) {
                bool c1 = (col + 1 < OW);
                if (row < OH) {
                    float* po = outb + (size_t)row * OW + col;
                    po[0] = d[0];
                    if (c1) po[1] = d[1];
                }
                if (row + 8 < OH) {
                    float* po = outb + (size_t)(row + 8) * OW + col;
                    po[0] = d[2];
                    if (c1) po[1] = d[3];
                }
            }
        }
    }
}

extern "C" void kernel_launch(void* const* d_in, const int* in_sizes, int n_in,
                              void* d_out, int out_size)
{
    const float* x    = (const float*)d_in[0];   // (64, 1024, 1024) f32
    const float* kern = (const float*)d_in[1];   // (16, 16) f32
    float* out = (float*)d_out;                  // (64, 1009, 1009) f32

    // Build the Toeplitz weight image (depends only on kern; deterministic).
    build_bw_kernel<<<(BW_ROWS * BW_PITCH + 255) / 256, 256>>>(kern);

    cudaFuncSetAttribute(conv2d_hmma_r14_kernel,
                         cudaFuncAttributeMaxDynamicSharedMemorySize, SMEM_DYN);

    dim3 grid((OW + TILE_OX - 1) / TILE_OX,   // 16
              (OH + TILE_OY - 1) / TILE_OY,   // 8
              Bn);                            // 64
    conv2d_hmma_r14_kernel<<<grid, NTHREADS, SMEM_DYN>>>(x, out);
}

// round 15
// speedup vs baseline: 2.9988x; 1.0158x over previous
#include <cuda_runtime.h>
#include <cuda_fp16.h>
#include <cstdint>

// ---------------- problem constants ----------------
#define KH 16
#define KW 16
#define Bn 64
#define Hn 1024
#define Wn 1024
#define OH 1009
#define OW 1009

// ---------------- tiling ----------------
// Block: 256 threads = 8 warps stacked in y. Block output tile 128y x 64x.
// Warp output tile 16y x 64x = 4 q-groups x 2 n-halves of m16n8.
// Precision: X and W both plain fp16 (single MMA pass); measured rel_err ~3e-4.
#define TILE_OY 128
#define TILE_OX 64
#define XROWS   143               // input rows needed: 128+15
#define XCOLS   80                // input cols needed: 64+15 (+1 spare)
#define XPITCH  88                // fp16/row -> 176B; ldmatrix conflict-free
#define XBYTES  (XROWS * XPITCH * 2)          // 25168
#define X_OFF   0
#define BW_OFF  XBYTES                        // 25168 (16B aligned)
#define BW_PITCH 40               // 80B rows; conflict-free for ldmatrix.trans
#define BW_ROWS  (16 * 16)        // ky * t = 256
#define BW_BYTES (BW_ROWS * BW_PITCH * 2)     // 20480
#define SMEM_DYN (BW_OFF + BW_BYTES)          // 45648 -> 3 CTAs/SM
#define NTHREADS 256

// Precomputed Toeplitz-weight smem image (exact byte layout), built by a tiny
// pre-kernel into device scratch, then block-copied from (hot) L2.
__device__ uint4 g_bw[BW_BYTES / 16];         // 1280 x uint4

// ---------------- PTX helpers (sm_80-class; compile for compute_103) ----
__device__ __forceinline__ uint32_t smem_u32(const void* p) {
    uint32_t a;
    asm("{ .reg .u64 t; cvta.to.shared.u64 t, %1; cvt.u32.u64 %0, t; }" : "=r"(a) : "l"(p));
    return a;
}
__device__ __forceinline__ void ldsm_x4(uint32_t* r, uint32_t addr) {
    asm volatile("ldmatrix.sync.aligned.m8n8.x4.shared.b16 {%0,%1,%2,%3}, [%4];"
                 : "=r"(r[0]), "=r"(r[1]), "=r"(r[2]), "=r"(r[3]) : "r"(addr));
}
__device__ __forceinline__ void ldsm_x4_t(uint32_t* r, uint32_t addr) {
    asm volatile("ldmatrix.sync.aligned.m8n8.x4.trans.shared.b16 {%0,%1,%2,%3}, [%4];"
                 : "=r"(r[0]), "=r"(r[1]), "=r"(r[2]), "=r"(r[3]) : "r"(addr));
}
// D(16x8,f32) += A(16x16,f16 row) * B(16x8,f16 col)
__device__ __forceinline__ void mma_f16(float* d, const uint32_t* a, const uint32_t* b) {
    asm volatile(
        "mma.sync.aligned.m16n8k16.row.col.f32.f16.f16.f32 "
        "{%0,%1,%2,%3}, {%4,%5,%6,%7}, {%8,%9}, {%0,%1,%2,%3};"
        : "+f"(d[0]), "+f"(d[1]), "+f"(d[2]), "+f"(d[3])
        : "r"(a[0]), "r"(a[1]), "r"(a[2]), "r"(a[3]), "r"(b[0]), "r"(b[1]));
}

// ---------------- pre-kernel: build Toeplitz weight image (plain fp16) -----
// Row r = ky*16 + t ; col c = v*16 + n (c >= 32 is zero padding)
// Bv[t][n] = w[ky, 16v + t - n] if in range else 0
__global__ void build_bw_kernel(const float* __restrict__ kern) {
    int idx = blockIdx.x * blockDim.x + threadIdx.x;   // over BW_ROWS * BW_PITCH
    if (idx >= BW_ROWS * BW_PITCH) return;
    int r  = idx / BW_PITCH;
    int c  = idx - r * BW_PITCH;
    int ky = r >> 4;
    int t  = r & 15;
    __half val = __float2half_rn(0.0f);
    if (c < 32) {
        int v  = c >> 4;
        int n  = c & 15;
        int kx = 16 * v + t - n;
        if (kx >= 0 && kx < KW)
            val = __float2half_rn(kern[ky * KW + kx]);
    }
    reinterpret_cast<__half*>(g_bw)[idx] = val;
}

extern __shared__ char dynsm[];

__global__ __launch_bounds__(NTHREADS, 3)
void conv2d_hmma_r15_kernel(const float* __restrict__ x,
                            float* __restrict__ out)
{
    const int tid  = threadIdx.x;
    const int lane = tid & 31;
    const int wid  = tid >> 5;
    const int b    = blockIdx.z;
    const int y0   = blockIdx.y * TILE_OY;
    const int x0   = blockIdx.x * TILE_OX;

    __half* X = reinterpret_cast<__half*>(dynsm + X_OFF);

    // ---- copy Toeplitz weight image from device scratch (L2-hot) ----
    {
        uint4* dstq = reinterpret_cast<uint4*>(dynsm + BW_OFF);
        #pragma unroll
        for (int i = 0; i < BW_BYTES / 16 / NTHREADS; i++)      // 5 iters
            dstq[tid + i * NTHREADS] = g_bw[tid + i * NTHREADS];
    }

    // ---- fill X tile as fp16 (clamped reads feed only discarded outputs) ----
    const float* __restrict__ xb = x + (size_t)b * (Hn * (size_t)Wn);
    for (int idx = tid; idx < XROWS * XCOLS; idx += NTHREADS) {
        int r = idx / XCOLS;
        int c = idx - r * XCOLS;
        int gy = y0 + r; if (gy > Hn - 1) gy = Hn - 1;
        int gx = x0 + c; if (gx > Wn - 1) gx = Wn - 1;
        X[r * XPITCH + c] = __float2half_rn(xb[(size_t)gy * Wn + gx]);
    }
    __syncthreads();

    // ---- per-warp / per-lane constants ----
    const int oyw = 16 * wid;        // warp row base within tile (0..112)

    const int mat  = lane >> 3;      // ldmatrix matrix index 0..3
    const int rr   = lane & 7;
    const int grow = rr + 8 * (mat & 1);
    const int g8   = (mat >> 1) * 8;
    const uint32_t sm_base = smem_u32(dynsm);

    // Strength-reduced base addresses (incremented per ky).
    uint32_t a_addr = sm_base + X_OFF
                    + (uint32_t)((oyw + grow) * XPITCH + g8) * 2;
    uint32_t b_addr = sm_base + BW_OFF
                    + (uint32_t)(grow * BW_PITCH + g8) * 2;

    float acc[4][2][4];              // [q][nh][4]
    #pragma unroll
    for (int j = 0; j < 4; j++)
        #pragma unroll
        for (int k = 0; k < 2; k++)
            #pragma unroll
            for (int l = 0; l < 4; l++) acc[j][k][l] = 0.0f;

    // ky loop: unroll 4 -> ptxas pipelines next-iteration LDSMs under MMAs.
    #pragma unroll 4
    for (int ky = 0; ky < KH; ky++) {
        // A fragments: 5 col-panels (16 cols each, covering 80 input cols)
        uint32_t A[5][4];
        #pragma unroll
        for (int p = 0; p < 5; p++)
            ldsm_x4(A[p], a_addr + (uint32_t)(p * 32));
        // B fragments: [v][4]: regs 0,1 = n-half 0 (k0/k1); regs 2,3 = n-half 1
        uint32_t Bv[2][4];
        #pragma unroll
        for (int v = 0; v < 2; v++)
            ldsm_x4_t(Bv[v], b_addr + (uint32_t)(v * 32));
        // 16 MMAs: q x v x nhalf
        #pragma unroll
        for (int q = 0; q < 4; q++) {
            #pragma unroll
            for (int v = 0; v < 2; v++) {
                const uint32_t* a = A[q + v];
                mma_f16(acc[q][0], a, &Bv[v][0]);
                mma_f16(acc[q][1], a, &Bv[v][2]);
            }
        }
        a_addr += XPITCH * 2;                 // next input row
        b_addr += 16 * BW_PITCH * 2;          // next ky weight block
    }

    // ---- epilogue: D frag (m16n8): d0=(g,c) d1=(g,c+1) d2=(g+8,c) d3=(g+8,c+1) ----
    float* __restrict__ outb = out + (size_t)b * (OH * (size_t)OW);
    const int g  = lane >> 2;
    const int c2 = (lane & 3) * 2;
    #pragma unroll
    for (int q = 0; q < 4; q++) {
        #pragma unroll
        for (int nh = 0; nh < 2; nh++) {
            const float* d = acc[q][nh];
            int row = y0 + oyw + g;
            int col = x0 + 16 * q + 8 * nh + c2;
            if (col < OW) {
                bool c1 = (col + 1 < OW);
                if (row < OH) {
                    float* po = outb + (size_t)row * OW + col;
                    po[0] = d[0];
                    if (c1) po[1] = d[1];
                }
                if (row + 8 < OH) {
                    float* po = outb + (size_t)(row + 8) * OW + col;
                    po[0] = d[2];
                    if (c1) po[1] = d[3];
                }
            }
        }
    }
}

extern "C" void kernel_launch(void* const* d_in, const int* in_sizes, int n_in,
                              void* d_out, int out_size)
{
    const float* x    = (const float*)d_in[0];   // (64, 1024, 1024) f32
    const float* kern = (const float*)d_in[1];   // (16, 16) f32
    float* out = (float*)d_out;                  // (64, 1009, 1009) f32

    // Build the Toeplitz weight image (depends only on kern; deterministic).
    build_bw_kernel<<<(BW_ROWS * BW_PITCH + 255) / 256, 256>>>(kern);

    cudaFuncSetAttribute(conv2d_hmma_r15_kernel,
                         cudaFuncAttributeMaxDynamicSharedMemorySize, SMEM_DYN);

    dim3 grid((OW + TILE_OX - 1) / TILE_OX,   // 16
              (OH + TILE_OY - 1) / TILE_OY,   // 8
              Bn);                            // 64
    conv2d_hmma_r15_kernel<<<grid, NTHREADS, SMEM_DYN>>>(x, out);
}